// round 4
// baseline (speedup 1.0000x reference)
#include <cuda_runtime.h>
#include <cstdint>

// Persistent-grid config: 148 SMs x 4 blocks x 512 threads = full chip.
#define NBLOCKS 592
#define NTHREADS 512
#define NWARPS (NTHREADS / 32)

__device__ float g_partials[NBLOCKS];
__device__ unsigned int g_count = 0;

// Fast exp(x): round-to-int trick + degree-4 poly of 2^f. FFMA-only, no MUFU.
// Rel err ~4e-5; final answer is 2 - 2*mean(p_t) ~ 2, so this is far inside
// the 1e-3 tolerance.
__device__ __forceinline__ float fexp(float x) {
    float z  = fmaf(x, 1.4426950408889634f, 12582912.0f);
    int   n  = __float_as_int(z) - 0x4B400000;
    float nf = z - 12582912.0f;
    float f  = fmaf(x, 1.4426950408889634f, -nf);
    float p = fmaf(f,
               fmaf(f,
                fmaf(f,
                 fmaf(f, 0.009618129842071848f, 0.05550410866482158f),
                 0.24022650695910072f),
                0.6931471805599453f),
               1.0f);
    return __int_as_float(__float_as_int(p) + (n << 23));
}

__global__ void __launch_bounds__(NTHREADS)
mae_fused_kernel(const float* __restrict__ logits,
                 const int* __restrict__ targets,   // int32 (JAX demotes int64)
                 float* __restrict__ out,
                 int B, int C, float invB)
{
    const int lane  = threadIdx.x & 31;
    const int warp  = threadIdx.x >> 5;
    const int gwarp = blockIdx.x * NWARPS + warp;
    const int total_warps = NBLOCKS * NWARPS;
    const int C4 = C >> 2;

    __shared__ float s_p[NWARPS];
    __shared__ bool  s_last;

    // ---- grid-stride warp-per-row main loop ----
    float psum = 0.0f;   // lane 0 accumulates p_t over this warp's rows
    for (int row = gwarp; row < B; row += total_warps) {
        const size_t base = (size_t)row * (size_t)C;
        const float4* rp = reinterpret_cast<const float4*>(logits + base);

        float a0 = 0.0f, a1 = 0.0f, a2 = 0.0f, a3 = 0.0f;
        #pragma unroll 4
        for (int j = lane; j < C4; j += 32) {
            float4 v = __ldcs(rp + j);     // streaming: no reuse
            a0 += fexp(v.x);
            a1 += fexp(v.y);
            a2 += fexp(v.z);
            a3 += fexp(v.w);
        }
        // scalar tail (C % 4 != 0; unused for C=1000, kept general)
        for (int c = (C4 << 2) + lane; c < C; c += 32)
            a0 += fexp(__ldcs(logits + base + c));

        float acc = (a0 + a1) + (a2 + a3);
        #pragma unroll
        for (int o = 16; o; o >>= 1)
            acc += __shfl_xor_sync(0xFFFFFFFFu, acc, o);

        if (lane == 0) {
            int t = targets[row];
            t = (t < 0) ? 0 : ((t >= C) ? C - 1 : t);   // defensive clamp
            float xt = __ldg(logits + base + (size_t)t);
            psum += fexp(xt) / acc;
        }
    }

    // ---- block reduction of per-warp sums ----
    if (lane == 0) s_p[warp] = psum;
    __syncthreads();

    if (threadIdx.x == 0) {
        float bsum = 0.0f;
        #pragma unroll
        for (int w = 0; w < NWARPS; w++) bsum += s_p[w];
        g_partials[blockIdx.x] = bsum;
        __threadfence();
        unsigned int t = atomicAdd(&g_count, 1u);
        s_last = (t == NBLOCKS - 1);
    }
    __syncthreads();

    // ---- last block performs the final (deterministic-order) reduction ----
    if (s_last) {
        __shared__ float sh[NWARPS];
        float s = 0.0f;
        for (int i = threadIdx.x; i < NBLOCKS; i += NTHREADS)
            s += __ldcg(&g_partials[i]);   // bypass L1: other blocks' writes

        #pragma unroll
        for (int o = 16; o; o >>= 1)
            s += __shfl_xor_sync(0xFFFFFFFFu, s, o);
        if (lane == 0) sh[warp] = s;
        __syncthreads();

        if (threadIdx.x < 32) {
            float v = (threadIdx.x < NWARPS) ? sh[threadIdx.x] : 0.0f;
            #pragma unroll
            for (int o = 16; o; o >>= 1)
                v += __shfl_xor_sync(0xFFFFFFFFu, v, o);
            if (threadIdx.x == 0) {
                out[0] = 2.0f - 2.0f * v * invB;
                g_count = 0;               // reset for next graph replay
            }
        }
    }
}

extern "C" void kernel_launch(void* const* d_in, const int* in_sizes, int n_in,
                              void* d_out, int out_size)
{
    const float* logits  = (const float*)d_in[0];
    const int*   targets = (const int*)d_in[1];
    float*       out     = (float*)d_out;

    const int B = in_sizes[1];
    const int C = in_sizes[0] / B;

    mae_fused_kernel<<<NBLOCKS, NTHREADS>>>(logits, targets, out,
                                            B, C, 1.0f / (float)B);
}

// round 5
// speedup vs baseline: 1.1901x; 1.1901x over previous
#include <cuda_runtime.h>
#include <cstdint>

// One row per warp, 8 warps (256 threads) per block.
#define RPB 8
#define MAX_PARTIALS 32768
__device__ float g_partials[MAX_PARTIALS];
__device__ unsigned int g_count = 0;

// Fast exp(x): round-to-int trick + degree-4 poly of 2^f. FFMA-only, no MUFU.
// Safe (no exponent wraparound) for x in about [-100, 80].
__device__ __forceinline__ float fexp(float x) {
    float z  = fmaf(x, 1.4426950408889634f, 12582912.0f);
    int   n  = __float_as_int(z) - 0x4B400000;
    float nf = z - 12582912.0f;
    float f  = fmaf(x, 1.4426950408889634f, -nf);
    float p = fmaf(f,
               fmaf(f,
                fmaf(f,
                 fmaf(f, 0.009618129842071848f, 0.05550410866482158f),
                 0.24022650695910072f),
                0.6931471805599453f),
               1.0f);
    return __int_as_float(__float_as_int(p) + (n << 23));
}

__global__ void __launch_bounds__(256)
mae_kernel(const float* __restrict__ logits,
           const int* __restrict__ targets,     // int32 (JAX demotes int64)
           float* __restrict__ out,
           int B, int C, float invB, int nblocks)
{
    const int lane = threadIdx.x & 31;
    const int warp = threadIdx.x >> 5;
    const int row  = blockIdx.x * RPB + warp;

    __shared__ float s_p[RPB];
    __shared__ bool  s_last;

    float p_t = 0.0f;
    if (row < B) {
        const size_t base = (size_t)row * (size_t)C;
        const float4* rp = reinterpret_cast<const float4*>(logits + base);
        const int C4 = C >> 2;

        // Batch up to 8 independent 16B loads per thread (MLP=8), covering
        // 8*32*4 = 1024 >= C elements. OOB slots get -80 -> fexp ~ 2^-115 ~ 0.
        float4 v[8];
        #pragma unroll
        for (int k = 0; k < 8; k++) {
            int j = lane + (k << 5);
            if (j < C4) v[k] = rp[j];
            else        v[k] = make_float4(-80.0f, -80.0f, -80.0f, -80.0f);
        }

        // Overlap target gather+exp with the poly evaluation below.
        float ext = 0.0f;
        if (lane == 0) {
            int t = targets[row];
            t = (t < 0) ? 0 : ((t >= C) ? C - 1 : t);
            ext = fexp(__ldg(logits + base + (size_t)t));
        }

        float a0 = 0.0f, a1 = 0.0f, a2 = 0.0f, a3 = 0.0f;
        #pragma unroll
        for (int k = 0; k < 8; k++) {
            a0 += fexp(v[k].x);
            a1 += fexp(v[k].y);
            a2 += fexp(v[k].z);
            a3 += fexp(v[k].w);
        }
        // generic tail for C not divisible by 4 or C > 1024 (unused at C=1000)
        for (int c = (C4 << 2) + lane; c < C; c += 32)
            a0 += fexp(logits[base + c]);
        for (int j = lane + 256; j < C4; j += 32) {
            float4 w = rp[j];
            a0 += fexp(w.x); a1 += fexp(w.y); a2 += fexp(w.z); a3 += fexp(w.w);
        }

        float acc = (a0 + a1) + (a2 + a3);
        #pragma unroll
        for (int o = 16; o; o >>= 1)
            acc += __shfl_xor_sync(0xFFFFFFFFu, acc, o);

        if (lane == 0) p_t = ext / acc;
    }

    if (lane == 0) s_p[warp] = p_t;
    __syncthreads();

    if (threadIdx.x == 0) {
        float bsum = 0.0f;
        #pragma unroll
        for (int w = 0; w < RPB; w++) bsum += s_p[w];
        g_partials[blockIdx.x] = bsum;
        __threadfence();
        unsigned int t = atomicAdd(&g_count, 1u);
        s_last = (t == (unsigned)nblocks - 1u);
    }
    __syncthreads();

    // Last arriving block: deterministic-order final reduction.
    if (s_last) {
        __shared__ float sh[8];
        float s = 0.0f;
        for (int i = threadIdx.x; i < nblocks; i += 256)
            s += __ldcg(&g_partials[i]);

        #pragma unroll
        for (int o = 16; o; o >>= 1)
            s += __shfl_xor_sync(0xFFFFFFFFu, s, o);
        if (lane == 0) sh[warp] = s;
        __syncthreads();

        if (threadIdx.x < 32) {
            float v2 = (threadIdx.x < 8) ? sh[threadIdx.x] : 0.0f;
            #pragma unroll
            for (int o = 16; o; o >>= 1)
                v2 += __shfl_xor_sync(0xFFFFFFFFu, v2, o);
            if (threadIdx.x == 0) {
                out[0] = 2.0f - 2.0f * v2 * invB;
                g_count = 0;   // reset for next graph replay
            }
        }
    }
}

extern "C" void kernel_launch(void* const* d_in, const int* in_sizes, int n_in,
                              void* d_out, int out_size)
{
    const float* logits  = (const float*)d_in[0];
    const int*   targets = (const int*)d_in[1];
    float*       out     = (float*)d_out;

    const int B = in_sizes[1];
    const int C = in_sizes[0] / B;

    int grid = (B + RPB - 1) / RPB;        // 16384 for B=131072
    if (grid > MAX_PARTIALS) grid = MAX_PARTIALS;

    mae_kernel<<<grid, 256>>>(logits, targets, out, B, C, 1.0f / (float)B, grid);
}